// round 1
// baseline (speedup 1.0000x reference)
#include <cuda_runtime.h>
#include <cuda_bf16.h>
#include <cstdint>

// Problem constants (fixed-shape problem)
#define NN 100000
#define NE 1600000
#define FD 64
#define SCAN_B 1024
#define NBLK ((NN + SCAN_B - 1) / SCAN_B)   // 98
#define EPS 1e-16f

// ---------------- scratch (device globals; no allocation allowed) ------------
__device__ float g_h[NN * FD];      // transformed features (current layer input to agg)
__device__ float g_agg[NN * FD];    // aggregated output of a layer
__device__ float g_ssrc[NN];
__device__ float g_sdst[NN];
__device__ int   g_deg[NN];
__device__ int   g_rp[NN + 1];
__device__ int   g_cursor[NN];
__device__ int   g_csrc[NE];
__device__ int   g_bsums[128];
__device__ int   g_boffs[128];

__device__ __forceinline__ float leaky(float v) {
    // NEG_SLOPE = 0.2 (valid max-form since slope > 0)
    return fmaxf(v, 0.2f * v);
}

// ---------------- CSR build ------------------------------------------------
__global__ void k_hist(const int* __restrict__ dst) {
    for (int e = blockIdx.x * blockDim.x + threadIdx.x; e < NE;
         e += gridDim.x * blockDim.x)
        atomicAdd(&g_deg[dst[e]], 1);
}

__global__ void k_scan_local() {
    __shared__ int sh[SCAN_B];
    int t = threadIdx.x;
    int idx = blockIdx.x * SCAN_B + t;
    int x = (idx < NN) ? g_deg[idx] : 0;
    sh[t] = x;
    __syncthreads();
    for (int off = 1; off < SCAN_B; off <<= 1) {
        int v = sh[t];
        if (t >= off) v += sh[t - off];
        __syncthreads();
        sh[t] = v;
        __syncthreads();
    }
    if (idx < NN) g_rp[idx] = sh[t] - x;      // exclusive
    if (t == SCAN_B - 1) g_bsums[blockIdx.x] = sh[t];
}

__global__ void k_scan_sums() {
    __shared__ int sh[128];
    int t = threadIdx.x;
    int x = (t < NBLK) ? g_bsums[t] : 0;
    sh[t] = x;
    __syncthreads();
    for (int off = 1; off < 128; off <<= 1) {
        int v = sh[t];
        if (t >= off) v += sh[t - off];
        __syncthreads();
        sh[t] = v;
        __syncthreads();
    }
    if (t < NBLK) g_boffs[t] = sh[t] - x;     // exclusive
}

__global__ void k_scan_add() {
    int i = blockIdx.x * blockDim.x + threadIdx.x;
    if (i < NN) {
        int v = g_rp[i] + g_boffs[i / SCAN_B];
        g_rp[i] = v;
        g_cursor[i] = v;
    }
    if (i == 0) g_rp[NN] = NE;
}

__global__ void k_scatter(const int* __restrict__ src, const int* __restrict__ dst) {
    for (int e = blockIdx.x * blockDim.x + threadIdx.x; e < NE;
         e += gridDim.x * blockDim.x) {
        int d = dst[e];
        int pos = atomicAdd(&g_cursor[d], 1);
        g_csrc[pos] = src[e];
    }
}

// ---------------- h = act(x) @ W  (64x64 GEMM, 64 rows / block) -------------
__global__ void __launch_bounds__(256) k_lin(
    const float* __restrict__ xin, const float* __restrict__ W,
    const float* __restrict__ b_in, int do_tanh, float* __restrict__ hout)
{
    __shared__ float Ws[64 * 64];
    __shared__ float Xs[64][65];
    int t = threadIdx.x;
    int row0 = blockIdx.x * 64;

    for (int i = t; i < 4096; i += 256) Ws[i] = W[i];
    for (int i = t; i < 4096; i += 256) {
        int r = i >> 6, c = i & 63;
        float v = 0.f;
        if (row0 + r < NN) {
            v = xin[(row0 + r) * 64 + c];
            if (do_tanh) v = tanhf(v + b_in[c]);
        }
        Xs[r][c] = v;
    }
    __syncthreads();

    int j0 = (t & 15) * 4;
    int g  = t >> 4;            // 0..15, 4 rows each
    float acc[4][4] = {};
#pragma unroll 8
    for (int k = 0; k < 64; k++) {
        float4 w = *(const float4*)&Ws[k * 64 + j0];
#pragma unroll
        for (int rr = 0; rr < 4; rr++) {
            float xv = Xs[g * 4 + rr][k];
            acc[rr][0] += xv * w.x;
            acc[rr][1] += xv * w.y;
            acc[rr][2] += xv * w.z;
            acc[rr][3] += xv * w.w;
        }
    }
#pragma unroll
    for (int rr = 0; rr < 4; rr++) {
        int r = g * 4 + rr;
        if (row0 + r < NN)
            *(float4*)&hout[(row0 + r) * 64 + j0] =
                make_float4(acc[rr][0], acc[rr][1], acc[rr][2], acc[rr][3]);
    }
}

// ---------------- per-node attention scores ---------------------------------
__global__ void k_scores(const float* __restrict__ h,
                         const float* __restrict__ asrc,
                         const float* __restrict__ adst)
{
    int warp = (blockIdx.x * blockDim.x + threadIdx.x) >> 5;
    int lane = threadIdx.x & 31;
    if (warp >= NN) return;
    float2 hv = *(const float2*)&h[warp * 64 + lane * 2];
    float2 as = *(const float2*)&asrc[lane * 2];
    float2 ad = *(const float2*)&adst[lane * 2];
    float ps = hv.x * as.x + hv.y * as.y;
    float pd = hv.x * ad.x + hv.y * ad.y;
#pragma unroll
    for (int o = 16; o; o >>= 1) {
        ps += __shfl_xor_sync(~0u, ps, o);
        pd += __shfl_xor_sync(~0u, pd, o);
    }
    if (!lane) {
        g_ssrc[warp] = ps;
        g_sdst[warp] = pd;
    }
}

// ---------------- GAT aggregation: warp per destination node ----------------
// pass1: segment max (incl. self loop) in registers
// pass2: acc = sum exp(e-m)*h[src], denom = sum exp(e-m); out = acc/(denom+eps)
__global__ void __launch_bounds__(256) k_node(const float* __restrict__ h,
                                              float* __restrict__ out)
{
    int warp = (blockIdx.x * blockDim.x + threadIdx.x) >> 5;
    int lane = threadIdx.x & 31;
    if (warp >= NN) return;
    int i = warp;
    int r0 = g_rp[i], r1 = g_rp[i + 1];
    float sd = g_sdst[i];
    float eself = leaky(g_ssrc[i] + sd);

    float m = eself;
    for (int e = r0 + lane; e < r1; e += 32) {
        int s = g_csrc[e];
        m = fmaxf(m, leaky(g_ssrc[s] + sd));
    }
#pragma unroll
    for (int o = 16; o; o >>= 1) m = fmaxf(m, __shfl_xor_sync(~0u, m, o));

    float ex = __expf(eself - m);
    float denom = ex;
    float a0 = ex * h[i * 64 + lane];
    float a1 = ex * h[i * 64 + 32 + lane];

    for (int e = r0; e < r1; e++) {
        int s = g_csrc[e];                        // uniform across warp
        float w = __expf(leaky(g_ssrc[s] + sd) - m);
        denom += w;
        a0 += w * h[s * 64 + lane];
        a1 += w * h[s * 64 + 32 + lane];
    }
    float inv = 1.f / (denom + EPS);
    out[i * 64 + lane]      = a0 * inv;
    out[i * 64 + 32 + lane] = a1 * inv;
}

// ---------------- final linear: out = (agg2 + b2) @ Wl + bl -----------------
__global__ void k_final(const float* __restrict__ agg,
                        const float* __restrict__ b2,
                        const float* __restrict__ Wl,
                        const float* __restrict__ bl,
                        float* __restrict__ out)
{
    int warp = (blockIdx.x * blockDim.x + threadIdx.x) >> 5;
    int lane = threadIdx.x & 31;
    if (warp >= NN) return;
    float2 hv = *(const float2*)&agg[warp * 64 + lane * 2];
    float2 bv = *(const float2*)&b2[lane * 2];
    float2 wv = *(const float2*)&Wl[lane * 2];
    float s = (hv.x + bv.x) * wv.x + (hv.y + bv.y) * wv.y;
#pragma unroll
    for (int o = 16; o; o >>= 1) s += __shfl_xor_sync(~0u, s, o);
    if (!lane) out[warp] = s + bl[0];
}

// ---------------- launcher ---------------------------------------------------
extern "C" void kernel_launch(void* const* d_in, const int* in_sizes, int n_in,
                              void* d_out, int out_size)
{
    const float* x     = (const float*)d_in[0];
    const int*   eidx  = (const int*)d_in[1];
    const float* W1    = (const float*)d_in[2];
    const float* as1   = (const float*)d_in[3];
    const float* ad1   = (const float*)d_in[4];
    const float* b1    = (const float*)d_in[5];
    const float* W2    = (const float*)d_in[6];
    const float* as2   = (const float*)d_in[7];
    const float* ad2   = (const float*)d_in[8];
    const float* b2    = (const float*)d_in[9];
    const float* Wl    = (const float*)d_in[10];
    const float* bl    = (const float*)d_in[11];
    float* out = (float*)d_out;

    const int* src = eidx;
    const int* dst = eidx + NE;

    void* deg_ptr = nullptr;
    cudaGetSymbolAddress(&deg_ptr, g_deg);
    float* h_ptr   = nullptr;
    float* agg_ptr = nullptr;
    cudaGetSymbolAddress((void**)&h_ptr, g_h);
    cudaGetSymbolAddress((void**)&agg_ptr, g_agg);

    const int LIN_BLOCKS  = (NN + 63) / 64;        // 1563
    const int WARP_BLOCKS = (NN * 32 + 255) / 256; // 12500
    const int EDGE_BLOCKS = 2048;

    // ---- CSR build (once; shared by both layers) ----
    cudaMemsetAsync(deg_ptr, 0, NN * sizeof(int));
    k_hist<<<EDGE_BLOCKS, 256>>>(dst);
    k_scan_local<<<NBLK, SCAN_B>>>();
    k_scan_sums<<<1, 128>>>();
    k_scan_add<<<(NN + 256) / 256, 256>>>();
    k_scatter<<<EDGE_BLOCKS, 256>>>(src, dst);

    // ---- layer 1 ----
    k_lin<<<LIN_BLOCKS, 256>>>(x, W1, nullptr, 0, h_ptr);
    k_scores<<<WARP_BLOCKS, 256>>>(h_ptr, as1, ad1);
    k_node<<<WARP_BLOCKS, 256>>>(h_ptr, agg_ptr);

    // ---- layer 2 (input = tanh(agg1 + b1)) ----
    k_lin<<<LIN_BLOCKS, 256>>>(agg_ptr, W2, b1, 1, h_ptr);
    k_scores<<<WARP_BLOCKS, 256>>>(h_ptr, as2, ad2);
    k_node<<<WARP_BLOCKS, 256>>>(h_ptr, agg_ptr);

    // ---- readout ----
    k_final<<<WARP_BLOCKS, 256>>>(agg_ptr, b2, Wl, bl, out);
}

// round 2
// speedup vs baseline: 1.0255x; 1.0255x over previous
#include <cuda_runtime.h>
#include <cuda_bf16.h>
#include <cstdint>

// Problem constants (fixed-shape problem)
#define NN 100000
#define NE 1600000
#define FD 64
#define SCAN_B 1024
#define NBLK ((NN + SCAN_B - 1) / SCAN_B)   // 98
#define EPS 1e-16f

// ---------------- scratch (device globals; no allocation allowed) ------------
__device__ float g_h[NN * FD];      // transformed features
__device__ float g_agg[NN * FD];    // aggregated output of a layer
__device__ float g_ssrc[NN];
__device__ float g_sdst[NN];
__device__ float g_esrc[NE];        // per-edge gathered src score (CSR order)
__device__ int   g_deg[NN];
__device__ int   g_rp[NN + 1];
__device__ int   g_cursor[NN];
__device__ int   g_csrc[NE];
__device__ int   g_bsums[128];
__device__ int   g_boffs[128];

__device__ __forceinline__ float leaky(float v) {
    return fmaxf(v, 0.2f * v);   // NEG_SLOPE = 0.2
}

// ---------------- CSR build ------------------------------------------------
__global__ void k_hist(const int* __restrict__ dst) {
    for (int e = blockIdx.x * blockDim.x + threadIdx.x; e < NE;
         e += gridDim.x * blockDim.x)
        atomicAdd(&g_deg[dst[e]], 1);
}

__global__ void k_scan_local() {
    __shared__ int sh[SCAN_B];
    int t = threadIdx.x;
    int idx = blockIdx.x * SCAN_B + t;
    int x = (idx < NN) ? g_deg[idx] : 0;
    sh[t] = x;
    __syncthreads();
    for (int off = 1; off < SCAN_B; off <<= 1) {
        int v = sh[t];
        if (t >= off) v += sh[t - off];
        __syncthreads();
        sh[t] = v;
        __syncthreads();
    }
    if (idx < NN) g_rp[idx] = sh[t] - x;      // exclusive
    if (t == SCAN_B - 1) g_bsums[blockIdx.x] = sh[t];
}

__global__ void k_scan_sums() {
    __shared__ int sh[128];
    int t = threadIdx.x;
    int x = (t < NBLK) ? g_bsums[t] : 0;
    sh[t] = x;
    __syncthreads();
    for (int off = 1; off < 128; off <<= 1) {
        int v = sh[t];
        if (t >= off) v += sh[t - off];
        __syncthreads();
        sh[t] = v;
        __syncthreads();
    }
    if (t < NBLK) g_boffs[t] = sh[t] - x;     // exclusive
}

__global__ void k_scan_add() {
    int i = blockIdx.x * blockDim.x + threadIdx.x;
    if (i < NN) {
        int v = g_rp[i] + g_boffs[i / SCAN_B];
        g_rp[i] = v;
        g_cursor[i] = v;
    }
    if (i == 0) g_rp[NN] = NE;
}

__global__ void k_scatter(const int* __restrict__ src, const int* __restrict__ dst) {
    for (int e = blockIdx.x * blockDim.x + threadIdx.x; e < NE;
         e += gridDim.x * blockDim.x) {
        int d = dst[e];
        int pos = atomicAdd(&g_cursor[d], 1);
        g_csrc[pos] = src[e];
    }
}

// ---------------- h = act(x) @ W  + fused per-node attention scores ---------
__global__ void __launch_bounds__(256) k_lin(
    const float* __restrict__ xin, const float* __restrict__ W,
    const float* __restrict__ b_in, int do_tanh, float* __restrict__ hout,
    const float* __restrict__ asrc, const float* __restrict__ adst)
{
    __shared__ float Ws[64 * 64];
    __shared__ float Xs[64][65];
    int t = threadIdx.x;
    int row0 = blockIdx.x * 64;

    for (int i = t; i < 4096; i += 256) Ws[i] = W[i];
    for (int i = t; i < 4096; i += 256) {
        int r = i >> 6, c = i & 63;
        float v = 0.f;
        if (row0 + r < NN) {
            v = xin[(row0 + r) * 64 + c];
            if (do_tanh) v = tanhf(v + b_in[c]);
        }
        Xs[r][c] = v;
    }
    __syncthreads();

    int j0 = (t & 15) * 4;
    int g  = t >> 4;            // 0..15, 4 rows each
    float acc[4][4] = {};
#pragma unroll 8
    for (int k = 0; k < 64; k++) {
        float4 w = *(const float4*)&Ws[k * 64 + j0];
#pragma unroll
        for (int rr = 0; rr < 4; rr++) {
            float xv = Xs[g * 4 + rr][k];
            acc[rr][0] += xv * w.x;
            acc[rr][1] += xv * w.y;
            acc[rr][2] += xv * w.z;
            acc[rr][3] += xv * w.w;
        }
    }
#pragma unroll
    for (int rr = 0; rr < 4; rr++) {
        int r = g * 4 + rr;
        if (row0 + r < NN)
            *(float4*)&hout[(row0 + r) * 64 + j0] =
                make_float4(acc[rr][0], acc[rr][1], acc[rr][2], acc[rr][3]);
    }

    // fused attention scores: ssrc = h·a_src, sdst = h·a_dst (per row)
    float4 As = *(const float4*)&asrc[j0];
    float4 Ad = *(const float4*)&adst[j0];
#pragma unroll
    for (int rr = 0; rr < 4; rr++) {
        float ps = acc[rr][0] * As.x + acc[rr][1] * As.y +
                   acc[rr][2] * As.z + acc[rr][3] * As.w;
        float pd = acc[rr][0] * Ad.x + acc[rr][1] * Ad.y +
                   acc[rr][2] * Ad.z + acc[rr][3] * Ad.w;
#pragma unroll
        for (int off = 8; off; off >>= 1) {
            ps += __shfl_down_sync(~0u, ps, off, 16);
            pd += __shfl_down_sync(~0u, pd, off, 16);
        }
        int r = row0 + g * 4 + rr;
        if ((t & 15) == 0 && r < NN) {
            g_ssrc[r] = ps;
            g_sdst[r] = pd;
        }
    }
}

// ---------------- per-edge gather of src scores (CSR order) -----------------
__global__ void k_edge() {
    for (int e = blockIdx.x * blockDim.x + threadIdx.x; e < NE;
         e += gridDim.x * blockDim.x)
        g_esrc[e] = g_ssrc[g_csrc[e]];
}

// ---------------- GAT aggregation: warp per destination node ----------------
__global__ void __launch_bounds__(256) k_node(const float* __restrict__ h,
                                              float* __restrict__ out)
{
    int warp = (blockIdx.x * blockDim.x + threadIdx.x) >> 5;
    int lane = threadIdx.x & 31;
    if (warp >= NN) return;
    int i = warp;
    int r0 = g_rp[i], r1 = g_rp[i + 1];
    float sd = g_sdst[i];
    float eself = leaky(g_ssrc[i] + sd);

    // pass 1: segment max (lane-parallel coalesced over esrc)
    float m = eself;
    for (int e = r0 + lane; e < r1; e += 32)
        m = fmaxf(m, leaky(g_esrc[e] + sd));
#pragma unroll
    for (int o = 16; o; o >>= 1) m = fmaxf(m, __shfl_xor_sync(~0u, m, o));

    float ex = __expf(eself - m);
    float denom = ex;
    float a0 = ex * h[i * 64 + lane];
    float a1 = ex * h[i * 64 + 32 + lane];

    // pass 2: unrolled x4 with independent loads (MLP ~16)
    int e = r0;
    for (; e + 4 <= r1; e += 4) {
        float w0 = g_esrc[e],     w1 = g_esrc[e + 1];
        float w2 = g_esrc[e + 2], w3 = g_esrc[e + 3];
        int s0 = g_csrc[e],     s1 = g_csrc[e + 1];
        int s2 = g_csrc[e + 2], s3 = g_csrc[e + 3];
        float h00 = h[s0 * 64 + lane], h01 = h[s0 * 64 + 32 + lane];
        float h10 = h[s1 * 64 + lane], h11 = h[s1 * 64 + 32 + lane];
        float h20 = h[s2 * 64 + lane], h21 = h[s2 * 64 + 32 + lane];
        float h30 = h[s3 * 64 + lane], h31 = h[s3 * 64 + 32 + lane];
        float e0 = __expf(leaky(w0 + sd) - m);
        float e1 = __expf(leaky(w1 + sd) - m);
        float e2 = __expf(leaky(w2 + sd) - m);
        float e3 = __expf(leaky(w3 + sd) - m);
        denom += e0 + e1 + e2 + e3;
        a0 += e0 * h00 + e1 * h10 + e2 * h20 + e3 * h30;
        a1 += e0 * h01 + e1 * h11 + e2 * h21 + e3 * h31;
    }
    for (; e < r1; e++) {
        int s = g_csrc[e];
        float w = __expf(leaky(g_esrc[e] + sd) - m);
        denom += w;
        a0 += w * h[s * 64 + lane];
        a1 += w * h[s * 64 + 32 + lane];
    }
    float inv = 1.f / (denom + EPS);
    out[i * 64 + lane]      = a0 * inv;
    out[i * 64 + 32 + lane] = a1 * inv;
}

// ---------------- final linear: out = (agg2 + b2) @ Wl + bl -----------------
__global__ void k_final(const float* __restrict__ agg,
                        const float* __restrict__ b2,
                        const float* __restrict__ Wl,
                        const float* __restrict__ bl,
                        float* __restrict__ out)
{
    int warp = (blockIdx.x * blockDim.x + threadIdx.x) >> 5;
    int lane = threadIdx.x & 31;
    if (warp >= NN) return;
    float2 hv = *(const float2*)&agg[warp * 64 + lane * 2];
    float2 bv = *(const float2*)&b2[lane * 2];
    float2 wv = *(const float2*)&Wl[lane * 2];
    float s = (hv.x + bv.x) * wv.x + (hv.y + bv.y) * wv.y;
#pragma unroll
    for (int o = 16; o; o >>= 1) s += __shfl_xor_sync(~0u, s, o);
    if (!lane) out[warp] = s + bl[0];
}

// ---------------- launcher ---------------------------------------------------
extern "C" void kernel_launch(void* const* d_in, const int* in_sizes, int n_in,
                              void* d_out, int out_size)
{
    const float* x     = (const float*)d_in[0];
    const int*   eidx  = (const int*)d_in[1];
    const float* W1    = (const float*)d_in[2];
    const float* as1   = (const float*)d_in[3];
    const float* ad1   = (const float*)d_in[4];
    const float* b1    = (const float*)d_in[5];
    const float* W2    = (const float*)d_in[6];
    const float* as2   = (const float*)d_in[7];
    const float* ad2   = (const float*)d_in[8];
    const float* b2    = (const float*)d_in[9];
    const float* Wl    = (const float*)d_in[10];
    const float* bl    = (const float*)d_in[11];
    float* out = (float*)d_out;

    const int* src = eidx;
    const int* dst = eidx + NE;

    void* deg_ptr = nullptr;
    cudaGetSymbolAddress(&deg_ptr, g_deg);
    float* h_ptr   = nullptr;
    float* agg_ptr = nullptr;
    cudaGetSymbolAddress((void**)&h_ptr, g_h);
    cudaGetSymbolAddress((void**)&agg_ptr, g_agg);

    const int LIN_BLOCKS  = (NN + 63) / 64;        // 1563
    const int WARP_BLOCKS = (NN * 32 + 255) / 256; // 12500
    const int EDGE_BLOCKS = 2048;

    // ---- CSR build (once; shared by both layers) ----
    cudaMemsetAsync(deg_ptr, 0, NN * sizeof(int));
    k_hist<<<EDGE_BLOCKS, 256>>>(dst);
    k_scan_local<<<NBLK, SCAN_B>>>();
    k_scan_sums<<<1, 128>>>();
    k_scan_add<<<(NN + 256) / 256, 256>>>();
    k_scatter<<<EDGE_BLOCKS, 256>>>(src, dst);

    // ---- layer 1 ----
    k_lin<<<LIN_BLOCKS, 256>>>(x, W1, nullptr, 0, h_ptr, as1, ad1);
    k_edge<<<EDGE_BLOCKS, 256>>>();
    k_node<<<WARP_BLOCKS, 256>>>(h_ptr, agg_ptr);

    // ---- layer 2 (input = tanh(agg1 + b1)) ----
    k_lin<<<LIN_BLOCKS, 256>>>(agg_ptr, W2, b1, 1, h_ptr, as2, ad2);
    k_edge<<<EDGE_BLOCKS, 256>>>();
    k_node<<<WARP_BLOCKS, 256>>>(h_ptr, agg_ptr);

    // ---- readout ----
    k_final<<<WARP_BLOCKS, 256>>>(agg_ptr, b2, Wl, bl, out);
}

// round 3
// speedup vs baseline: 1.2210x; 1.1907x over previous
#include <cuda_runtime.h>
#include <cuda_bf16.h>
#include <cuda_fp16.h>
#include <cstdint>

// Problem constants (fixed-shape problem)
#define NN 100000
#define NE 1600000
#define SCAN_B 1024
#define NBLK ((NN + SCAN_B - 1) / SCAN_B)   // 98
#define EPS 1e-16f

// ---------------- scratch (device globals; no allocation allowed) ------------
__device__ __half2 g_h2[NN * 32];   // transformed features, fp16 (64 feats = 32 half2)
__device__ float g_agg[NN * 64];    // aggregated output of a layer (fp32)
__device__ float g_ssrc[NN];
__device__ float g_sdst[NN];
__device__ int   g_deg[NN];
__device__ int   g_rp[NN + 1];
__device__ int   g_cursor[NN];
__device__ int   g_csrc[NE];
__device__ int   g_bsums[128];

__device__ __forceinline__ float leaky(float v) {
    return fmaxf(v, 0.2f * v);   // NEG_SLOPE = 0.2
}

// ---------------- CSR build ------------------------------------------------
__global__ void k_hist(const int4* __restrict__ dst4) {
    for (int e = blockIdx.x * blockDim.x + threadIdx.x; e < NE / 4;
         e += gridDim.x * blockDim.x) {
        int4 d = dst4[e];
        atomicAdd(&g_deg[d.x], 1);
        atomicAdd(&g_deg[d.y], 1);
        atomicAdd(&g_deg[d.z], 1);
        atomicAdd(&g_deg[d.w], 1);
    }
}

__global__ void k_scan_local() {
    __shared__ int sh[SCAN_B];
    int t = threadIdx.x;
    int idx = blockIdx.x * SCAN_B + t;
    int x = (idx < NN) ? g_deg[idx] : 0;
    sh[t] = x;
    __syncthreads();
    for (int off = 1; off < SCAN_B; off <<= 1) {
        int v = sh[t];
        if (t >= off) v += sh[t - off];
        __syncthreads();
        sh[t] = v;
        __syncthreads();
    }
    if (idx < NN) g_rp[idx] = sh[t] - x;      // exclusive local
    if (t == SCAN_B - 1) g_bsums[blockIdx.x] = sh[t];
}

// merged: scan block sums (redundantly per block, 98 values) + add offsets
__global__ void k_scan_merge() {
    __shared__ int sh[128];
    int t = threadIdx.x;
    if (t < 128) sh[t] = (t < NBLK) ? g_bsums[t] : 0;
    __syncthreads();
    for (int off = 1; off < 128; off <<= 1) {
        int v = 0;
        if (t < 128) { v = sh[t]; if (t >= off) v += sh[t - off]; }
        __syncthreads();
        if (t < 128) sh[t] = v;
        __syncthreads();
    }
    int i = blockIdx.x * blockDim.x + t;
    if (i < NN) {
        int b = i >> 10;
        int off = (b == 0) ? 0 : sh[b - 1];
        int v = g_rp[i] + off;
        g_rp[i] = v;
        g_cursor[i] = v;
    }
    if (i == 0) g_rp[NN] = NE;
}

__global__ void k_scatter(const int4* __restrict__ src4, const int4* __restrict__ dst4) {
    for (int e = blockIdx.x * blockDim.x + threadIdx.x; e < NE / 4;
         e += gridDim.x * blockDim.x) {
        int4 s = src4[e];
        int4 d = dst4[e];
        g_csrc[atomicAdd(&g_cursor[d.x], 1)] = s.x;
        g_csrc[atomicAdd(&g_cursor[d.y], 1)] = s.y;
        g_csrc[atomicAdd(&g_cursor[d.z], 1)] = s.z;
        g_csrc[atomicAdd(&g_cursor[d.w], 1)] = s.w;
    }
}

// ---------------- h = act(x) @ W  + fused per-node attention scores ---------
// output h in fp16 (half2), scores in fp32
__global__ void __launch_bounds__(256) k_lin(
    const float* __restrict__ xin, const float* __restrict__ W,
    const float* __restrict__ b_in, int do_tanh, __half2* __restrict__ hout,
    const float* __restrict__ asrc, const float* __restrict__ adst)
{
    __shared__ float Ws[64 * 64];
    __shared__ float Xs[64][65];
    int t = threadIdx.x;
    int row0 = blockIdx.x * 64;

    for (int i = t; i < 4096; i += 256) Ws[i] = W[i];
    for (int i = t; i < 4096; i += 256) {
        int r = i >> 6, c = i & 63;
        float v = 0.f;
        if (row0 + r < NN) {
            v = xin[(row0 + r) * 64 + c];
            if (do_tanh) v = tanhf(v + b_in[c]);
        }
        Xs[r][c] = v;
    }
    __syncthreads();

    int j0 = (t & 15) * 4;
    int g  = t >> 4;            // 0..15, 4 rows each
    float acc[4][4] = {};
#pragma unroll 8
    for (int k = 0; k < 64; k++) {
        float4 w = *(const float4*)&Ws[k * 64 + j0];
#pragma unroll
        for (int rr = 0; rr < 4; rr++) {
            float xv = Xs[g * 4 + rr][k];
            acc[rr][0] += xv * w.x;
            acc[rr][1] += xv * w.y;
            acc[rr][2] += xv * w.z;
            acc[rr][3] += xv * w.w;
        }
    }
#pragma unroll
    for (int rr = 0; rr < 4; rr++) {
        int r = row0 + g * 4 + rr;
        if (r < NN) {
            __half2 o0 = __floats2half2_rn(acc[rr][0], acc[rr][1]);
            __half2 o1 = __floats2half2_rn(acc[rr][2], acc[rr][3]);
            __half2* hp = &hout[r * 32 + (j0 >> 1)];
            hp[0] = o0;
            hp[1] = o1;
        }
    }

    // fused attention scores: ssrc = h·a_src, sdst = h·a_dst (per row)
    float4 As = *(const float4*)&asrc[j0];
    float4 Ad = *(const float4*)&adst[j0];
#pragma unroll
    for (int rr = 0; rr < 4; rr++) {
        float ps = acc[rr][0] * As.x + acc[rr][1] * As.y +
                   acc[rr][2] * As.z + acc[rr][3] * As.w;
        float pd = acc[rr][0] * Ad.x + acc[rr][1] * Ad.y +
                   acc[rr][2] * Ad.z + acc[rr][3] * Ad.w;
#pragma unroll
        for (int off = 8; off; off >>= 1) {
            ps += __shfl_down_sync(~0u, ps, off, 16);
            pd += __shfl_down_sync(~0u, pd, off, 16);
        }
        int r = row0 + g * 4 + rr;
        if ((t & 15) == 0 && r < NN) {
            g_ssrc[r] = ps;
            g_sdst[r] = pd;
        }
    }
}

// ---------------- GAT aggregation: warp per destination node ----------------
// single pass, no max-shift (scores bounded; clamp guards overflow, result
// mathematically identical to max-shifted softmax)
__global__ void __launch_bounds__(256) k_node(const __half2* __restrict__ h2,
                                              float* __restrict__ out)
{
    int warp = (blockIdx.x * blockDim.x + threadIdx.x) >> 5;
    int lane = threadIdx.x & 31;
    if (warp >= NN) return;
    int i = warp;
    int r0 = g_rp[i], r1 = g_rp[i + 1];
    float sd = g_sdst[i];

    float ex = __expf(fminf(leaky(g_ssrc[i] + sd), 60.f));   // self loop
    float2 hs = __half22float2(h2[i * 32 + lane]);
    float ax = ex * hs.x, ay = ex * hs.y;
    float dl = 0.f;                       // per-lane partial of denom (edges)

    for (int eb = r0; eb < r1; eb += 32) {
        int idx = eb + lane;
        int   s_l = i;
        float w_l = 0.f;
        if (idx < r1) {
            s_l = g_csrc[idx];
            w_l = __expf(fminf(leaky(g_ssrc[s_l] + sd), 60.f));
        }
        dl += w_l;
        int n  = min(32, r1 - eb);
        int jn = (n + 3) & ~3;            // pad to 4 (padded lanes have w=0)
        for (int j = 0; j < jn; j += 4) {
            int   s0 = __shfl_sync(~0u, s_l, j);
            int   s1 = __shfl_sync(~0u, s_l, j + 1);
            int   s2 = __shfl_sync(~0u, s_l, j + 2);
            int   s3 = __shfl_sync(~0u, s_l, j + 3);
            float w0 = __shfl_sync(~0u, w_l, j);
            float w1 = __shfl_sync(~0u, w_l, j + 1);
            float w2 = __shfl_sync(~0u, w_l, j + 2);
            float w3 = __shfl_sync(~0u, w_l, j + 3);
            float2 f0 = __half22float2(h2[s0 * 32 + lane]);
            float2 f1 = __half22float2(h2[s1 * 32 + lane]);
            float2 f2 = __half22float2(h2[s2 * 32 + lane]);
            float2 f3 = __half22float2(h2[s3 * 32 + lane]);
            ax += w0 * f0.x + w1 * f1.x + w2 * f2.x + w3 * f3.x;
            ay += w0 * f0.y + w1 * f1.y + w2 * f2.y + w3 * f3.y;
        }
    }
#pragma unroll
    for (int o = 16; o; o >>= 1) dl += __shfl_xor_sync(~0u, dl, o);
    float inv = 1.f / (ex + dl + EPS);
    out[i * 64 + lane * 2]     = ax * inv;
    out[i * 64 + lane * 2 + 1] = ay * inv;
}

// ---------------- final linear: out = (agg2 + b2) @ Wl + bl -----------------
__global__ void k_final(const float* __restrict__ agg,
                        const float* __restrict__ b2,
                        const float* __restrict__ Wl,
                        const float* __restrict__ bl,
                        float* __restrict__ out)
{
    int warp = (blockIdx.x * blockDim.x + threadIdx.x) >> 5;
    int lane = threadIdx.x & 31;
    if (warp >= NN) return;
    float2 hv = *(const float2*)&agg[warp * 64 + lane * 2];
    float2 bv = *(const float2*)&b2[lane * 2];
    float2 wv = *(const float2*)&Wl[lane * 2];
    float s = (hv.x + bv.x) * wv.x + (hv.y + bv.y) * wv.y;
#pragma unroll
    for (int o = 16; o; o >>= 1) s += __shfl_xor_sync(~0u, s, o);
    if (!lane) out[warp] = s + bl[0];
}

// ---------------- launcher ---------------------------------------------------
extern "C" void kernel_launch(void* const* d_in, const int* in_sizes, int n_in,
                              void* d_out, int out_size)
{
    const float* x     = (const float*)d_in[0];
    const int*   eidx  = (const int*)d_in[1];
    const float* W1    = (const float*)d_in[2];
    const float* as1   = (const float*)d_in[3];
    const float* ad1   = (const float*)d_in[4];
    const float* b1    = (const float*)d_in[5];
    const float* W2    = (const float*)d_in[6];
    const float* as2   = (const float*)d_in[7];
    const float* ad2   = (const float*)d_in[8];
    const float* b2    = (const float*)d_in[9];
    const float* Wl    = (const float*)d_in[10];
    const float* bl    = (const float*)d_in[11];
    float* out = (float*)d_out;

    const int4* src4 = (const int4*)eidx;
    const int4* dst4 = (const int4*)(eidx + NE);

    void* deg_ptr = nullptr;
    cudaGetSymbolAddress(&deg_ptr, g_deg);
    __half2* h_ptr = nullptr;
    float* agg_ptr = nullptr;
    cudaGetSymbolAddress((void**)&h_ptr, g_h2);
    cudaGetSymbolAddress((void**)&agg_ptr, g_agg);

    const int LIN_BLOCKS  = (NN + 63) / 64;        // 1563
    const int WARP_BLOCKS = (NN * 32 + 255) / 256; // 12500
    const int EDGE_BLOCKS = 1024;

    // ---- CSR build (once; shared by both layers) ----
    cudaMemsetAsync(deg_ptr, 0, NN * sizeof(int));
    k_hist<<<EDGE_BLOCKS, 256>>>(dst4);
    k_scan_local<<<NBLK, SCAN_B>>>();
    k_scan_merge<<<(NN + 255) / 256, 256>>>();
    k_scatter<<<EDGE_BLOCKS, 256>>>(src4, dst4);

    // ---- layer 1 ----
    k_lin<<<LIN_BLOCKS, 256>>>(x, W1, nullptr, 0, h_ptr, as1, ad1);
    k_node<<<WARP_BLOCKS, 256>>>(h_ptr, agg_ptr);

    // ---- layer 2 (input = tanh(agg1 + b1)) ----
    k_lin<<<LIN_BLOCKS, 256>>>(agg_ptr, W2, b1, 1, h_ptr, as2, ad2);
    k_node<<<WARP_BLOCKS, 256>>>(h_ptr, agg_ptr);

    // ---- readout ----
    k_final<<<WARP_BLOCKS, 256>>>(agg_ptr, b2, Wl, bl, out);
}

// round 4
// speedup vs baseline: 1.2848x; 1.0522x over previous
#include <cuda_runtime.h>
#include <cuda_bf16.h>
#include <cuda_fp16.h>
#include <cstdint>

// Problem constants (fixed-shape problem)
#define NN 100000
#define NE 1600000
#define SCAN_NB 98                      // ceil(100000/1024)
#define EPS 1e-16f

// ---------------- scratch (device globals; no allocation allowed) ------------
__device__ __half2 g_h2[NN * 32];   // transformed features, fp16 (64 feats = 32 half2)
__device__ float g_agg[NN * 64];    // aggregated output of layer 1 (fp32)
__device__ float g_ssrc[NN];
__device__ float g_sdst[NN];
__device__ int   g_deg[NN];         // zero-init at load; re-zeroed by k_scan each run
__device__ int   g_cur[NN];         // exclusive prefix -> after scatter: inclusive
__device__ int   g_csrc[NE];
__device__ int   g_bsums[128];
__device__ int   g_done;            // k_scan completion counter (self-resetting)
__device__ int   g_epoch;           // k_scan epoch (monotonic across runs)

__device__ __forceinline__ float leaky(float v) {
    return fmaxf(v, 0.2f * v);   // NEG_SLOPE = 0.2
}

// ---------------- histogram of dst -----------------------------------------
__global__ void k_hist(const int4* __restrict__ dst4) {
    int e = blockIdx.x * blockDim.x + threadIdx.x;
    if (e < NE / 4) {
        int4 d = dst4[e];
        atomicAdd(&g_deg[d.x], 1);
        atomicAdd(&g_deg[d.y], 1);
        atomicAdd(&g_deg[d.z], 1);
        atomicAdd(&g_deg[d.w], 1);
    }
}

// ---------------- single-kernel exclusive scan of deg -> g_cur ---------------
// 98 blocks x 1024 threads, all co-resident (98 < 148 SMs). Each block scans
// its chunk, publishes its total, waits for all totals via an epoch flip, then
// applies its global offset. Also zeroes g_deg for the next run.
__global__ void __launch_bounds__(1024) k_scan() {
    __shared__ int swarp[32];
    __shared__ int sboff[128];
    int t = threadIdx.x, b = blockIdx.x;
    int lane = t & 31, wid = t >> 5;
    int idx = b * 1024 + t;

    int e0 = 0;
    if (t == 0) e0 = *(volatile int*)&g_epoch;   // read BEFORE publishing

    int v = (idx < NN) ? g_deg[idx] : 0;
    if (idx < NN) g_deg[idx] = 0;

    // block inclusive scan
    int x = v;
#pragma unroll
    for (int off = 1; off < 32; off <<= 1) {
        int y = __shfl_up_sync(~0u, x, off);
        if (lane >= off) x += y;
    }
    if (lane == 31) swarp[wid] = x;
    __syncthreads();
    if (wid == 0) {
        int s = swarp[lane];
#pragma unroll
        for (int off = 1; off < 32; off <<= 1) {
            int y = __shfl_up_sync(~0u, s, off);
            if (lane >= off) s += y;
        }
        swarp[lane] = s;
    }
    __syncthreads();
    int incl = x + (wid ? swarp[wid - 1] : 0);
    int ex = incl - v;
    int total = swarp[31];

    // publish + epoch barrier
    if (t == 0) {
        g_bsums[b] = total;
        __threadfence();
        int r = atomicAdd(&g_done, 1);
        if (r == SCAN_NB - 1) {
            g_done = 0;
            __threadfence();
            atomicAdd(&g_epoch, 1);
        }
        while (*(volatile int*)&g_epoch == e0) { }
    }
    __syncthreads();

    // prefix over the 98 block sums (Hillis-Steele in smem, 128 wide)
    if (t < 128) sboff[t] = (t < SCAN_NB) ? g_bsums[t] : 0;
    __syncthreads();
    for (int off = 1; off < 128; off <<= 1) {
        int y = 0;
        if (t < 128) { y = sboff[t]; if (t >= off) y += sboff[t - off]; }
        __syncthreads();
        if (t < 128) sboff[t] = y;
        __syncthreads();
    }
    int boff = b ? sboff[b - 1] : 0;
    if (idx < NN) g_cur[idx] = ex + boff;
}

// ---------------- CSR scatter (g_cur becomes inclusive prefix) ---------------
__global__ void k_scatter(const int4* __restrict__ src4, const int4* __restrict__ dst4) {
    int e = blockIdx.x * blockDim.x + threadIdx.x;
    if (e < NE / 4) {
        int4 s = src4[e];
        int4 d = dst4[e];
        g_csrc[atomicAdd(&g_cur[d.x], 1)] = s.x;
        g_csrc[atomicAdd(&g_cur[d.y], 1)] = s.y;
        g_csrc[atomicAdd(&g_cur[d.z], 1)] = s.z;
        g_csrc[atomicAdd(&g_cur[d.w], 1)] = s.w;
    }
}

// ---------------- h = act(x) @ W  + fused per-node attention scores ---------
__global__ void __launch_bounds__(256) k_lin(
    const float* __restrict__ xin, const float* __restrict__ W,
    const float* __restrict__ b_in, int do_tanh, __half2* __restrict__ hout,
    const float* __restrict__ asrc, const float* __restrict__ adst)
{
    __shared__ float Ws[64 * 64];
    __shared__ float Xs[64][65];
    int t = threadIdx.x;
    int row0 = blockIdx.x * 64;

    for (int i = t; i < 4096; i += 256) Ws[i] = W[i];
    for (int i = t; i < 4096; i += 256) {
        int r = i >> 6, c = i & 63;
        float v = 0.f;
        if (row0 + r < NN) {
            v = xin[(row0 + r) * 64 + c];
            if (do_tanh) v = tanhf(v + b_in[c]);
        }
        Xs[r][c] = v;
    }
    __syncthreads();

    int j0 = (t & 15) * 4;
    int g  = t >> 4;            // 0..15, 4 rows each
    float acc[4][4] = {};
#pragma unroll 8
    for (int k = 0; k < 64; k++) {
        float4 w = *(const float4*)&Ws[k * 64 + j0];
#pragma unroll
        for (int rr = 0; rr < 4; rr++) {
            float xv = Xs[g * 4 + rr][k];
            acc[rr][0] += xv * w.x;
            acc[rr][1] += xv * w.y;
            acc[rr][2] += xv * w.z;
            acc[rr][3] += xv * w.w;
        }
    }
#pragma unroll
    for (int rr = 0; rr < 4; rr++) {
        int r = row0 + g * 4 + rr;
        if (r < NN) {
            __half2 o0 = __floats2half2_rn(acc[rr][0], acc[rr][1]);
            __half2 o1 = __floats2half2_rn(acc[rr][2], acc[rr][3]);
            __half2* hp = &hout[r * 32 + (j0 >> 1)];
            hp[0] = o0;
            hp[1] = o1;
        }
    }

    float4 As = *(const float4*)&asrc[j0];
    float4 Ad = *(const float4*)&adst[j0];
#pragma unroll
    for (int rr = 0; rr < 4; rr++) {
        float ps = acc[rr][0] * As.x + acc[rr][1] * As.y +
                   acc[rr][2] * As.z + acc[rr][3] * As.w;
        float pd = acc[rr][0] * Ad.x + acc[rr][1] * Ad.y +
                   acc[rr][2] * Ad.z + acc[rr][3] * Ad.w;
#pragma unroll
        for (int off = 8; off; off >>= 1) {
            ps += __shfl_down_sync(~0u, ps, off, 16);
            pd += __shfl_down_sync(~0u, pd, off, 16);
        }
        int r = row0 + g * 4 + rr;
        if ((t & 15) == 0 && r < NN) {
            g_ssrc[r] = ps;
            g_sdst[r] = pd;
        }
    }
}

// ---------------- GAT aggregation: warp per destination node ----------------
// mode 0: write agg (fp32). mode 1: fused readout out[i] = (agg+b2)@Wl + bl.
__global__ void __launch_bounds__(256) k_node(const __half2* __restrict__ h2,
                                              float* __restrict__ aggout,
                                              const float* __restrict__ b2,
                                              const float* __restrict__ Wl,
                                              const float* __restrict__ bl,
                                              float* __restrict__ out,
                                              int final_mode)
{
    int warp = (blockIdx.x * blockDim.x + threadIdx.x) >> 5;
    int lane = threadIdx.x & 31;
    if (warp >= NN) return;
    int i = warp;
    int r0 = (i > 0) ? g_cur[i - 1] : 0;
    int r1 = g_cur[i];
    float sd = g_sdst[i];

    float ex = __expf(fminf(leaky(g_ssrc[i] + sd), 60.f));   // self loop
    float2 hs = __half22float2(h2[i * 32 + lane]);
    float ax = ex * hs.x, ay = ex * hs.y;
    float dl = 0.f;

    for (int eb = r0; eb < r1; eb += 32) {
        int idx = eb + lane;
        int   s_l = i;
        float w_l = 0.f;
        if (idx < r1) {
            s_l = g_csrc[idx];
            w_l = __expf(fminf(leaky(g_ssrc[s_l] + sd), 60.f));
        }
        dl += w_l;
        int n  = min(32, r1 - eb);
        int jn = (n + 3) & ~3;            // pad to 4 (padded lanes have w=0)
        for (int j = 0; j < jn; j += 4) {
            int   s0 = __shfl_sync(~0u, s_l, j);
            int   s1 = __shfl_sync(~0u, s_l, j + 1);
            int   s2 = __shfl_sync(~0u, s_l, j + 2);
            int   s3 = __shfl_sync(~0u, s_l, j + 3);
            float w0 = __shfl_sync(~0u, w_l, j);
            float w1 = __shfl_sync(~0u, w_l, j + 1);
            float w2 = __shfl_sync(~0u, w_l, j + 2);
            float w3 = __shfl_sync(~0u, w_l, j + 3);
            float2 f0 = __half22float2(h2[s0 * 32 + lane]);
            float2 f1 = __half22float2(h2[s1 * 32 + lane]);
            float2 f2 = __half22float2(h2[s2 * 32 + lane]);
            float2 f3 = __half22float2(h2[s3 * 32 + lane]);
            ax += w0 * f0.x + w1 * f1.x + w2 * f2.x + w3 * f3.x;
            ay += w0 * f0.y + w1 * f1.y + w2 * f2.y + w3 * f3.y;
        }
    }
#pragma unroll
    for (int o = 16; o; o >>= 1) dl += __shfl_xor_sync(~0u, dl, o);
    float inv = 1.f / (ex + dl + EPS);

    if (!final_mode) {
        aggout[i * 64 + lane * 2]     = ax * inv;
        aggout[i * 64 + lane * 2 + 1] = ay * inv;
    } else {
        float2 bv = *(const float2*)&b2[lane * 2];
        float2 wv = *(const float2*)&Wl[lane * 2];
        float s = (ax * inv + bv.x) * wv.x + (ay * inv + bv.y) * wv.y;
#pragma unroll
        for (int o = 16; o; o >>= 1) s += __shfl_xor_sync(~0u, s, o);
        if (!lane) out[i] = s + bl[0];
    }
}

// ---------------- launcher ---------------------------------------------------
extern "C" void kernel_launch(void* const* d_in, const int* in_sizes, int n_in,
                              void* d_out, int out_size)
{
    const float* x     = (const float*)d_in[0];
    const int*   eidx  = (const int*)d_in[1];
    const float* W1    = (const float*)d_in[2];
    const float* as1   = (const float*)d_in[3];
    const float* ad1   = (const float*)d_in[4];
    const float* b1    = (const float*)d_in[5];
    const float* W2    = (const float*)d_in[6];
    const float* as2   = (const float*)d_in[7];
    const float* ad2   = (const float*)d_in[8];
    const float* b2    = (const float*)d_in[9];
    const float* Wl    = (const float*)d_in[10];
    const float* bl    = (const float*)d_in[11];
    float* out = (float*)d_out;

    const int4* src4 = (const int4*)eidx;
    const int4* dst4 = (const int4*)(eidx + NE);

    __half2* h_ptr = nullptr;
    float* agg_ptr = nullptr;
    cudaGetSymbolAddress((void**)&h_ptr, g_h2);
    cudaGetSymbolAddress((void**)&agg_ptr, g_agg);

    const int LIN_BLOCKS  = (NN + 63) / 64;          // 1563
    const int WARP_BLOCKS = (NN * 32 + 255) / 256;   // 12500
    const int E4_BLOCKS   = (NE / 4 + 255) / 256;    // 1563

    // 1: layer-1 linear (independent of CSR)
    k_lin<<<LIN_BLOCKS, 256>>>(x, W1, nullptr, 0, h_ptr, as1, ad1);
    // 2-4: CSR build
    k_hist<<<E4_BLOCKS, 256>>>(dst4);
    k_scan<<<SCAN_NB, 1024>>>();
    k_scatter<<<E4_BLOCKS, 256>>>(src4, dst4);
    // 5: layer-1 aggregation  (profiled slot)
    k_node<<<WARP_BLOCKS, 256>>>(h_ptr, agg_ptr, nullptr, nullptr, nullptr, nullptr, 0);
    // 6: layer-2 linear (input = tanh(agg1 + b1))
    k_lin<<<LIN_BLOCKS, 256>>>(agg_ptr, W2, b1, 1, h_ptr, as2, ad2);
    // 7: layer-2 aggregation + fused readout
    k_node<<<WARP_BLOCKS, 256>>>(h_ptr, nullptr, b2, Wl, bl, out, 1);
}

// round 5
// speedup vs baseline: 1.2944x; 1.0074x over previous
#include <cuda_runtime.h>
#include <cuda_bf16.h>
#include <cuda_fp16.h>
#include <mma.h>
#include <cstdint>

using namespace nvcuda;

// Problem constants (fixed-shape problem)
#define NN 100000
#define NE 1600000
#define SCAN_NB 98                      // ceil(100000/1024)
#define EPS 1e-16f

// ---------------- scratch (device globals; no allocation allowed) ------------
__device__ __half2 g_h2[NN * 32];   // transformed features, fp16 (64 feats = 32 half2)
__device__ float g_agg[NN * 64];    // aggregated output of layer 1 (fp32)
__device__ float g_ssrc[NN];
__device__ float g_sdst[NN];
__device__ int   g_deg[NN];         // zero-init at load; re-zeroed by k_scan each run
__device__ int   g_cur[NN];         // exclusive prefix -> after scatter: inclusive
__device__ int   g_csrc[NE];
__device__ int   g_bsums[128];
__device__ int   g_done;            // k_scan completion counter (self-resetting)
__device__ int   g_epoch;           // k_scan epoch (monotonic across runs)

__device__ __forceinline__ float leaky(float v) {
    return fmaxf(v, 0.2f * v);   // NEG_SLOPE = 0.2
}

__device__ __forceinline__ float tanh_fast(float v) {
    asm("tanh.approx.f32 %0, %0;" : "+f"(v));
    return v;
}

// ---------------- histogram of dst -----------------------------------------
__global__ void k_hist(const int4* __restrict__ dst4) {
    int e = blockIdx.x * blockDim.x + threadIdx.x;
    if (e < NE / 4) {
        int4 d = dst4[e];
        atomicAdd(&g_deg[d.x], 1);
        atomicAdd(&g_deg[d.y], 1);
        atomicAdd(&g_deg[d.z], 1);
        atomicAdd(&g_deg[d.w], 1);
    }
}

// ---------------- single-kernel exclusive scan of deg -> g_cur ---------------
__global__ void __launch_bounds__(1024) k_scan() {
    __shared__ int swarp[32];
    __shared__ int sboff[128];
    int t = threadIdx.x, b = blockIdx.x;
    int lane = t & 31, wid = t >> 5;
    int idx = b * 1024 + t;

    int e0 = 0;
    if (t == 0) e0 = *(volatile int*)&g_epoch;   // read BEFORE publishing

    int v = (idx < NN) ? g_deg[idx] : 0;
    if (idx < NN) g_deg[idx] = 0;

    int x = v;
#pragma unroll
    for (int off = 1; off < 32; off <<= 1) {
        int y = __shfl_up_sync(~0u, x, off);
        if (lane >= off) x += y;
    }
    if (lane == 31) swarp[wid] = x;
    __syncthreads();
    if (wid == 0) {
        int s = swarp[lane];
#pragma unroll
        for (int off = 1; off < 32; off <<= 1) {
            int y = __shfl_up_sync(~0u, s, off);
            if (lane >= off) s += y;
        }
        swarp[lane] = s;
    }
    __syncthreads();
    int incl = x + (wid ? swarp[wid - 1] : 0);
    int ex = incl - v;
    int total = swarp[31];

    if (t == 0) {
        g_bsums[b] = total;
        __threadfence();
        int r = atomicAdd(&g_done, 1);
        if (r == SCAN_NB - 1) {
            g_done = 0;
            __threadfence();
            atomicAdd(&g_epoch, 1);
        }
        while (*(volatile int*)&g_epoch == e0) { }
    }
    __syncthreads();

    if (t < 128) sboff[t] = (t < SCAN_NB) ? g_bsums[t] : 0;
    __syncthreads();
    for (int off = 1; off < 128; off <<= 1) {
        int y = 0;
        if (t < 128) { y = sboff[t]; if (t >= off) y += sboff[t - off]; }
        __syncthreads();
        if (t < 128) sboff[t] = y;
        __syncthreads();
    }
    int boff = b ? sboff[b - 1] : 0;
    if (idx < NN) g_cur[idx] = ex + boff;
}

// ---------------- CSR scatter (g_cur becomes inclusive prefix) ---------------
__global__ void k_scatter(const int4* __restrict__ src4, const int4* __restrict__ dst4) {
    int e = blockIdx.x * blockDim.x + threadIdx.x;
    if (e < NE / 4) {
        int4 s = src4[e];
        int4 d = dst4[e];
        g_csrc[atomicAdd(&g_cur[d.x], 1)] = s.x;
        g_csrc[atomicAdd(&g_cur[d.y], 1)] = s.y;
        g_csrc[atomicAdd(&g_cur[d.z], 1)] = s.z;
        g_csrc[atomicAdd(&g_cur[d.w], 1)] = s.w;
    }
}

// ---------------- h = act(x) @ W via wmma + fused attention scores ----------
// fp16 inputs, fp32 accumulate. 64 rows per block, 8 warps (4 row-groups x 2
// col-groups of 32). Scores computed from fp32 accum in smem.
__global__ void __launch_bounds__(256) k_lin(
    const float* __restrict__ xin, const float* __restrict__ W,
    const float* __restrict__ b_in, int do_tanh, __half2* __restrict__ hout,
    const float* __restrict__ asrc, const float* __restrict__ adst)
{
    __shared__ __half Xh[64 * 72];
    __shared__ __half Wh[64 * 64];
    __shared__ float  Cs[64 * 72];
    int t = threadIdx.x;
    int row0 = blockIdx.x * 64;

    for (int i = t; i < 4096; i += 256) Wh[i] = __float2half(W[i]);
    for (int i = t; i < 4096; i += 256) {
        int r = i >> 6, c = i & 63;
        float v = 0.f;
        int gr = row0 + r;
        if (gr < NN) {
            v = xin[gr * 64 + c];
            if (do_tanh) v = tanh_fast(v + b_in[c]);
        }
        Xh[r * 72 + c] = __float2half(v);
    }
    __syncthreads();

    int w  = t >> 5;
    int wm = w & 3;     // row group (16 rows)
    int wn = w >> 2;    // col group (32 cols)
    wmma::fragment<wmma::accumulator, 16, 16, 16, float> c0, c1;
    wmma::fill_fragment(c0, 0.f);
    wmma::fill_fragment(c1, 0.f);
#pragma unroll
    for (int k0 = 0; k0 < 64; k0 += 16) {
        wmma::fragment<wmma::matrix_a, 16, 16, 16, __half, wmma::row_major> a;
        wmma::fragment<wmma::matrix_b, 16, 16, 16, __half, wmma::row_major> b0, b1;
        wmma::load_matrix_sync(a, Xh + wm * 16 * 72 + k0, 72);
        wmma::load_matrix_sync(b0, Wh + k0 * 64 + wn * 32, 64);
        wmma::load_matrix_sync(b1, Wh + k0 * 64 + wn * 32 + 16, 64);
        wmma::mma_sync(c0, a, b0, c0);
        wmma::mma_sync(c1, a, b1, c1);
    }
    wmma::store_matrix_sync(Cs + wm * 16 * 72 + wn * 32,      c0, 72, wmma::mem_row_major);
    wmma::store_matrix_sync(Cs + wm * 16 * 72 + wn * 32 + 16, c1, 72, wmma::mem_row_major);
    __syncthreads();

    // h out (fp16), coalesced
    for (int i = t; i < 2048; i += 256) {
        int r = i >> 5, c2 = i & 31;
        int gr = row0 + r;
        if (gr < NN)
            hout[gr * 32 + c2] =
                __floats2half2_rn(Cs[r * 72 + c2 * 2], Cs[r * 72 + c2 * 2 + 1]);
    }

    // scores: 4 threads per row, each covers 16 of 64 features
    int r = t >> 2, q = t & 3;
    const float* crow = &Cs[r * 72 + q * 16];
    float ps = 0.f, pd = 0.f;
#pragma unroll
    for (int j = 0; j < 16; j++) {
        float hv = crow[j];
        ps += hv * asrc[q * 16 + j];
        pd += hv * adst[q * 16 + j];
    }
    ps += __shfl_down_sync(~0u, ps, 2, 4);
    ps += __shfl_down_sync(~0u, ps, 1, 4);
    pd += __shfl_down_sync(~0u, pd, 2, 4);
    pd += __shfl_down_sync(~0u, pd, 1, 4);
    if (q == 0 && row0 + r < NN) {
        g_ssrc[row0 + r] = ps;
        g_sdst[row0 + r] = pd;
    }
}

// ---------------- GAT aggregation: warp per destination node ----------------
// mode 0: write agg (fp32). mode 1: fused readout out[i] = (agg+b2)@Wl + bl.
__global__ void __launch_bounds__(256) k_node(const __half2* __restrict__ h2,
                                              float* __restrict__ aggout,
                                              const float* __restrict__ b2,
                                              const float* __restrict__ Wl,
                                              const float* __restrict__ bl,
                                              float* __restrict__ out,
                                              int final_mode)
{
    int warp = (blockIdx.x * blockDim.x + threadIdx.x) >> 5;
    int lane = threadIdx.x & 31;
    if (warp >= NN) return;
    int i = warp;
    int r0 = (i > 0) ? g_cur[i - 1] : 0;
    int r1 = g_cur[i];
    float sd = g_sdst[i];

    float ex = __expf(fminf(leaky(g_ssrc[i] + sd), 60.f));   // self loop
    float2 hs = __half22float2(h2[i * 32 + lane]);
    float ax = ex * hs.x, ay = ex * hs.y;
    float dl = 0.f;

    for (int eb = r0; eb < r1; eb += 32) {
        int idx = eb + lane;
        int   s_l = i;
        float w_l = 0.f;
        if (idx < r1) {
            s_l = g_csrc[idx];
            w_l = __expf(fminf(leaky(g_ssrc[s_l] + sd), 60.f));
        }
        dl += w_l;
        int n  = min(32, r1 - eb);
        int jn = (n + 3) & ~3;            // pad to 4 (padded lanes have w=0)
        for (int j = 0; j < jn; j += 4) {
            int   s0 = __shfl_sync(~0u, s_l, j);
            int   s1 = __shfl_sync(~0u, s_l, j + 1);
            int   s2 = __shfl_sync(~0u, s_l, j + 2);
            int   s3 = __shfl_sync(~0u, s_l, j + 3);
            float w0 = __shfl_sync(~0u, w_l, j);
            float w1 = __shfl_sync(~0u, w_l, j + 1);
            float w2 = __shfl_sync(~0u, w_l, j + 2);
            float w3 = __shfl_sync(~0u, w_l, j + 3);
            float2 f0 = __half22float2(h2[s0 * 32 + lane]);
            float2 f1 = __half22float2(h2[s1 * 32 + lane]);
            float2 f2 = __half22float2(h2[s2 * 32 + lane]);
            float2 f3 = __half22float2(h2[s3 * 32 + lane]);
            ax += w0 * f0.x + w1 * f1.x + w2 * f2.x + w3 * f3.x;
            ay += w0 * f0.y + w1 * f1.y + w2 * f2.y + w3 * f3.y;
        }
    }
#pragma unroll
    for (int o = 16; o; o >>= 1) dl += __shfl_xor_sync(~0u, dl, o);
    float inv = 1.f / (ex + dl + EPS);

    if (!final_mode) {
        aggout[i * 64 + lane * 2]     = ax * inv;
        aggout[i * 64 + lane * 2 + 1] = ay * inv;
    } else {
        float2 bv = *(const float2*)&b2[lane * 2];
        float2 wv = *(const float2*)&Wl[lane * 2];
        float s = (ax * inv + bv.x) * wv.x + (ay * inv + bv.y) * wv.y;
#pragma unroll
        for (int o = 16; o; o >>= 1) s += __shfl_xor_sync(~0u, s, o);
        if (!lane) out[i] = s + bl[0];
    }
}

// ---------------- launcher ---------------------------------------------------
extern "C" void kernel_launch(void* const* d_in, const int* in_sizes, int n_in,
                              void* d_out, int out_size)
{
    const float* x     = (const float*)d_in[0];
    const int*   eidx  = (const int*)d_in[1];
    const float* W1    = (const float*)d_in[2];
    const float* as1   = (const float*)d_in[3];
    const float* ad1   = (const float*)d_in[4];
    const float* b1    = (const float*)d_in[5];
    const float* W2    = (const float*)d_in[6];
    const float* as2   = (const float*)d_in[7];
    const float* ad2   = (const float*)d_in[8];
    const float* b2    = (const float*)d_in[9];
    const float* Wl    = (const float*)d_in[10];
    const float* bl    = (const float*)d_in[11];
    float* out = (float*)d_out;

    const int4* src4 = (const int4*)eidx;
    const int4* dst4 = (const int4*)(eidx + NE);

    __half2* h_ptr = nullptr;
    float* agg_ptr = nullptr;
    cudaGetSymbolAddress((void**)&h_ptr, g_h2);
    cudaGetSymbolAddress((void**)&agg_ptr, g_agg);

    const int LIN_BLOCKS  = (NN + 63) / 64;          // 1563
    const int WARP_BLOCKS = (NN * 32 + 255) / 256;   // 12500
    const int E4_BLOCKS   = (NE / 4 + 255) / 256;    // 1563

    // 1: layer-1 linear (independent of CSR)
    k_lin<<<LIN_BLOCKS, 256>>>(x, W1, nullptr, 0, h_ptr, as1, ad1);
    // 2-4: CSR build
    k_hist<<<E4_BLOCKS, 256>>>(dst4);
    k_scan<<<SCAN_NB, 1024>>>();
    k_scatter<<<E4_BLOCKS, 256>>>(src4, dst4);
    // 5: layer-1 aggregation
    k_node<<<WARP_BLOCKS, 256>>>(h_ptr, agg_ptr, nullptr, nullptr, nullptr, nullptr, 0);
    // 6: layer-2 linear (input = tanh(agg1 + b1))
    k_lin<<<LIN_BLOCKS, 256>>>(agg_ptr, W2, b1, 1, h_ptr, as2, ad2);
    // 7: layer-2 aggregation + fused readout
    k_node<<<WARP_BLOCKS, 256>>>(h_ptr, nullptr, b2, Wl, bl, out, 1);
}

// round 6
// speedup vs baseline: 1.4206x; 1.0975x over previous
#include <cuda_runtime.h>
#include <cuda_bf16.h>
#include <cuda_fp16.h>
#include <mma.h>
#include <cstdint>

using namespace nvcuda;

// Problem constants (fixed-shape problem)
#define NN 100000
#define NE 1600000
#define SCAN_NB 98                      // ceil(100000/1024)
#define EPS 1e-16f

// ---------------- scratch (device globals; no allocation allowed) ------------
__device__ __half2 g_h2[NN * 32];   // transformed features, fp16 (64 feats = 32 half2)
__device__ float g_agg[NN * 64];    // aggregated output of layer 1 (fp32)
__device__ float g_ssrc[NN];
__device__ float g_sdst[NN];
__device__ int   g_deg[NN];         // zero-init at load; re-zeroed by k_scan each run
__device__ int   g_cur[NN];         // exclusive prefix -> after scatter: inclusive
__device__ int   g_csrc[NE];
__device__ int   g_bsums[128];
__device__ int   g_done;            // k_scan completion counter (self-resetting)
__device__ int   g_epoch;           // k_scan epoch (monotonic across runs)

__device__ __forceinline__ float leaky(float v) {
    return fmaxf(v, 0.2f * v);   // NEG_SLOPE = 0.2
}

__device__ __forceinline__ float tanh_fast(float v) {
    asm("tanh.approx.f32 %0, %0;" : "+f"(v));
    return v;
}

// ---------------- histogram of dst (8 independent chains / thread) ----------
__global__ void k_hist(const int4* __restrict__ dst4) {
    const int Q = NE / 8;               // 200000 (int4 pairs)
    int t = blockIdx.x * blockDim.x + threadIdx.x;
    if (t < Q) {
        int4 d0 = dst4[t];
        int4 d1 = dst4[t + Q];
        atomicAdd(&g_deg[d0.x], 1);
        atomicAdd(&g_deg[d0.y], 1);
        atomicAdd(&g_deg[d0.z], 1);
        atomicAdd(&g_deg[d0.w], 1);
        atomicAdd(&g_deg[d1.x], 1);
        atomicAdd(&g_deg[d1.y], 1);
        atomicAdd(&g_deg[d1.z], 1);
        atomicAdd(&g_deg[d1.w], 1);
    }
}

// ---------------- single-kernel exclusive scan of deg -> g_cur ---------------
__global__ void __launch_bounds__(1024) k_scan() {
    __shared__ int swarp[32];
    __shared__ int sboff[128];
    int t = threadIdx.x, b = blockIdx.x;
    int lane = t & 31, wid = t >> 5;
    int idx = b * 1024 + t;

    int e0 = 0;
    if (t == 0) e0 = *(volatile int*)&g_epoch;   // read BEFORE publishing

    int v = (idx < NN) ? g_deg[idx] : 0;
    if (idx < NN) g_deg[idx] = 0;

    int x = v;
#pragma unroll
    for (int off = 1; off < 32; off <<= 1) {
        int y = __shfl_up_sync(~0u, x, off);
        if (lane >= off) x += y;
    }
    if (lane == 31) swarp[wid] = x;
    __syncthreads();
    if (wid == 0) {
        int s = swarp[lane];
#pragma unroll
        for (int off = 1; off < 32; off <<= 1) {
            int y = __shfl_up_sync(~0u, s, off);
            if (lane >= off) s += y;
        }
        swarp[lane] = s;
    }
    __syncthreads();
    int incl = x + (wid ? swarp[wid - 1] : 0);
    int ex = incl - v;
    int total = swarp[31];

    if (t == 0) {
        g_bsums[b] = total;
        __threadfence();
        int r = atomicAdd(&g_done, 1);
        if (r == SCAN_NB - 1) {
            g_done = 0;
            __threadfence();
            atomicAdd(&g_epoch, 1);
        }
        while (*(volatile int*)&g_epoch == e0) { }
    }
    __syncthreads();

    if (t < 128) sboff[t] = (t < SCAN_NB) ? g_bsums[t] : 0;
    __syncthreads();
    for (int off = 1; off < 128; off <<= 1) {
        int y = 0;
        if (t < 128) { y = sboff[t]; if (t >= off) y += sboff[t - off]; }
        __syncthreads();
        if (t < 128) sboff[t] = y;
        __syncthreads();
    }
    int boff = b ? sboff[b - 1] : 0;
    if (idx < NN) g_cur[idx] = ex + boff;
}

// ---------------- CSR scatter (8 independent chains / thread) ----------------
__global__ void k_scatter(const int4* __restrict__ src4, const int4* __restrict__ dst4) {
    const int Q = NE / 8;
    int t = blockIdx.x * blockDim.x + threadIdx.x;
    if (t < Q) {
        int4 s0 = src4[t];
        int4 d0 = dst4[t];
        int4 s1 = src4[t + Q];
        int4 d1 = dst4[t + Q];
        g_csrc[atomicAdd(&g_cur[d0.x], 1)] = s0.x;
        g_csrc[atomicAdd(&g_cur[d0.y], 1)] = s0.y;
        g_csrc[atomicAdd(&g_cur[d0.z], 1)] = s0.z;
        g_csrc[atomicAdd(&g_cur[d0.w], 1)] = s0.w;
        g_csrc[atomicAdd(&g_cur[d1.x], 1)] = s1.x;
        g_csrc[atomicAdd(&g_cur[d1.y], 1)] = s1.y;
        g_csrc[atomicAdd(&g_cur[d1.z], 1)] = s1.z;
        g_csrc[atomicAdd(&g_cur[d1.w], 1)] = s1.w;
    }
}

// ---------------- h = act(x) @ W via wmma + fused attention scores ----------
__global__ void __launch_bounds__(256) k_lin(
    const float* __restrict__ xin, const float* __restrict__ W,
    const float* __restrict__ b_in, int do_tanh, __half2* __restrict__ hout,
    const float* __restrict__ asrc, const float* __restrict__ adst)
{
    __shared__ __half Xh[64 * 72];
    __shared__ __half Wh[64 * 64];
    __shared__ float  Cs[64 * 72];
    int t = threadIdx.x;
    int row0 = blockIdx.x * 64;

    for (int i = t; i < 4096; i += 256) Wh[i] = __float2half(W[i]);
    for (int i = t; i < 4096; i += 256) {
        int r = i >> 6, c = i & 63;
        float v = 0.f;
        int gr = row0 + r;
        if (gr < NN) {
            v = xin[gr * 64 + c];
            if (do_tanh) v = tanh_fast(v + b_in[c]);
        }
        Xh[r * 72 + c] = __float2half(v);
    }
    __syncthreads();

    int w  = t >> 5;
    int wm = w & 3;     // row group (16 rows)
    int wn = w >> 2;    // col group (32 cols)
    wmma::fragment<wmma::accumulator, 16, 16, 16, float> c0, c1;
    wmma::fill_fragment(c0, 0.f);
    wmma::fill_fragment(c1, 0.f);
#pragma unroll
    for (int k0 = 0; k0 < 64; k0 += 16) {
        wmma::fragment<wmma::matrix_a, 16, 16, 16, __half, wmma::row_major> a;
        wmma::fragment<wmma::matrix_b, 16, 16, 16, __half, wmma::row_major> b0, b1;
        wmma::load_matrix_sync(a, Xh + wm * 16 * 72 + k0, 72);
        wmma::load_matrix_sync(b0, Wh + k0 * 64 + wn * 32, 64);
        wmma::load_matrix_sync(b1, Wh + k0 * 64 + wn * 32 + 16, 64);
        wmma::mma_sync(c0, a, b0, c0);
        wmma::mma_sync(c1, a, b1, c1);
    }
    wmma::store_matrix_sync(Cs + wm * 16 * 72 + wn * 32,      c0, 72, wmma::mem_row_major);
    wmma::store_matrix_sync(Cs + wm * 16 * 72 + wn * 32 + 16, c1, 72, wmma::mem_row_major);
    __syncthreads();

    for (int i = t; i < 2048; i += 256) {
        int r = i >> 5, c2 = i & 31;
        int gr = row0 + r;
        if (gr < NN)
            hout[gr * 32 + c2] =
                __floats2half2_rn(Cs[r * 72 + c2 * 2], Cs[r * 72 + c2 * 2 + 1]);
    }

    int r = t >> 2, q = t & 3;
    const float* crow = &Cs[r * 72 + q * 16];
    float ps = 0.f, pd = 0.f;
#pragma unroll
    for (int j = 0; j < 16; j++) {
        float hv = crow[j];
        ps += hv * asrc[q * 16 + j];
        pd += hv * adst[q * 16 + j];
    }
    ps += __shfl_down_sync(~0u, ps, 2, 4);
    ps += __shfl_down_sync(~0u, ps, 1, 4);
    pd += __shfl_down_sync(~0u, pd, 2, 4);
    pd += __shfl_down_sync(~0u, pd, 1, 4);
    if (q == 0 && row0 + r < NN) {
        g_ssrc[row0 + r] = ps;
        g_sdst[row0 + r] = pd;
    }
}

// ---------------- GAT aggregation: warp per destination node ----------------
// smem-staged (s,w) pairs: gather loop reads uniform LDS broadcasts, no shfl
// dependency chain; 4 gathers in flight.
__global__ void __launch_bounds__(256) k_node(const __half2* __restrict__ h2,
                                              float* __restrict__ aggout,
                                              const float* __restrict__ b2,
                                              const float* __restrict__ Wl,
                                              const float* __restrict__ bl,
                                              float* __restrict__ out,
                                              int final_mode)
{
    __shared__ int   sS[8][32];
    __shared__ float sW[8][32];
    int warp = (blockIdx.x * blockDim.x + threadIdx.x) >> 5;
    int lane = threadIdx.x & 31;
    int w8   = (threadIdx.x >> 5) & 7;
    if (warp >= NN) return;
    int i = warp;
    int r0 = (i > 0) ? g_cur[i - 1] : 0;
    int r1 = g_cur[i];
    float sd = g_sdst[i];

    float ex = __expf(fminf(leaky(g_ssrc[i] + sd), 60.f));   // self loop
    float2 hs = __half22float2(h2[i * 32 + lane]);
    float ax = ex * hs.x, ay = ex * hs.y;
    float dl = 0.f;

    for (int eb = r0; eb < r1; eb += 32) {
        int idx = eb + lane;
        int   s_l = 0;
        float w_l = 0.f;
        if (idx < r1) {
            s_l = g_csrc[idx];
            w_l = __expf(fminf(leaky(g_ssrc[s_l] + sd), 60.f));
        }
        sS[w8][lane] = s_l;
        sW[w8][lane] = w_l;
        dl += w_l;
        __syncwarp();
        int n = min(32, r1 - eb);
        int j = 0;
        for (; j + 4 <= n; j += 4) {
            int   s0 = sS[w8][j],     s1 = sS[w8][j + 1];
            int   s2 = sS[w8][j + 2], s3 = sS[w8][j + 3];
            float w0 = sW[w8][j],     w1 = sW[w8][j + 1];
            float w2 = sW[w8][j + 2], w3 = sW[w8][j + 3];
            float2 f0 = __half22float2(h2[s0 * 32 + lane]);
            float2 f1 = __half22float2(h2[s1 * 32 + lane]);
            float2 f2 = __half22float2(h2[s2 * 32 + lane]);
            float2 f3 = __half22float2(h2[s3 * 32 + lane]);
            ax += w0 * f0.x + w1 * f1.x + w2 * f2.x + w3 * f3.x;
            ay += w0 * f0.y + w1 * f1.y + w2 * f2.y + w3 * f3.y;
        }
        for (; j < n; j++) {
            int   s0 = sS[w8][j];
            float w0 = sW[w8][j];
            float2 f0 = __half22float2(h2[s0 * 32 + lane]);
            ax += w0 * f0.x;
            ay += w0 * f0.y;
        }
        __syncwarp();
    }
#pragma unroll
    for (int o = 16; o; o >>= 1) dl += __shfl_xor_sync(~0u, dl, o);
    float inv = 1.f / (ex + dl + EPS);

    if (!final_mode) {
        aggout[i * 64 + lane * 2]     = ax * inv;
        aggout[i * 64 + lane * 2 + 1] = ay * inv;
    } else {
        float2 bv = *(const float2*)&b2[lane * 2];
        float2 wv = *(const float2*)&Wl[lane * 2];
        float s = (ax * inv + bv.x) * wv.x + (ay * inv + bv.y) * wv.y;
#pragma unroll
        for (int o = 16; o; o >>= 1) s += __shfl_xor_sync(~0u, s, o);
        if (!lane) out[i] = s + bl[0];
    }
}

// ---------------- launcher ---------------------------------------------------
static cudaStream_t s_csr = nullptr;
static cudaEvent_t  s_evFork = nullptr, s_evJoin = nullptr;

extern "C" void kernel_launch(void* const* d_in, const int* in_sizes, int n_in,
                              void* d_out, int out_size)
{
    const float* x     = (const float*)d_in[0];
    const int*   eidx  = (const int*)d_in[1];
    const float* W1    = (const float*)d_in[2];
    const float* as1   = (const float*)d_in[3];
    const float* ad1   = (const float*)d_in[4];
    const float* b1    = (const float*)d_in[5];
    const float* W2    = (const float*)d_in[6];
    const float* as2   = (const float*)d_in[7];
    const float* ad2   = (const float*)d_in[8];
    const float* b2    = (const float*)d_in[9];
    const float* Wl    = (const float*)d_in[10];
    const float* bl    = (const float*)d_in[11];
    float* out = (float*)d_out;

    const int4* src4 = (const int4*)eidx;
    const int4* dst4 = (const int4*)(eidx + NE);

    __half2* h_ptr = nullptr;
    float* agg_ptr = nullptr;
    cudaGetSymbolAddress((void**)&h_ptr, g_h2);
    cudaGetSymbolAddress((void**)&agg_ptr, g_agg);

    if (!s_csr) {
        cudaStreamCreateWithFlags(&s_csr, cudaStreamNonBlocking);
        cudaEventCreateWithFlags(&s_evFork, cudaEventDisableTiming);
        cudaEventCreateWithFlags(&s_evJoin, cudaEventDisableTiming);
    }

    const int LIN_BLOCKS  = (NN + 63) / 64;          // 1563
    const int WARP_BLOCKS = (NN * 32 + 255) / 256;   // 12500
    const int E8_BLOCKS   = (NE / 8 + 255) / 256;    // 782

    // fork: CSR build runs concurrently with layer-1 linear
    cudaEventRecord(s_evFork, 0);
    cudaStreamWaitEvent(s_csr, s_evFork, 0);

    k_lin<<<LIN_BLOCKS, 256>>>(x, W1, nullptr, 0, h_ptr, as1, ad1);

    k_hist<<<E8_BLOCKS, 256, 0, s_csr>>>(dst4);
    k_scan<<<SCAN_NB, 1024, 0, s_csr>>>();
    k_scatter<<<E8_BLOCKS, 256, 0, s_csr>>>(src4, dst4);
    cudaEventRecord(s_evJoin, s_csr);
    cudaStreamWaitEvent(0, s_evJoin, 0);

    // layer-1 aggregation
    k_node<<<WARP_BLOCKS, 256>>>(h_ptr, agg_ptr, nullptr, nullptr, nullptr, nullptr, 0);
    // layer-2 linear (input = tanh(agg1 + b1))
    k_lin<<<LIN_BLOCKS, 256>>>(agg_ptr, W2, b1, 1, h_ptr, as2, ad2);
    // layer-2 aggregation + fused readout
    k_node<<<WARP_BLOCKS, 256>>>(h_ptr, nullptr, b2, Wl, bl, out, 1);
}